// round 7
// baseline (speedup 1.0000x reference)
#include <cuda_runtime.h>
#include <cuda_bf16.h>
#include <float.h>

// LabelLoss: B=16, K=11, H=W=128, C=7 — single kernel, critical-path optimized.
//   pooled = 3x3 box-sum (pad 1) of heatmap[b,k]  (÷9 dropped: argmax-invariant)
//   idx    = argmax over flattened HxW (first occurrence)
//   loss[b,k] = sum_c (pred[b, k*7+c, idx/W, idx%W] - gt[b,k,c])^2
//   out[b] = mean_k loss[b,k]
//
// 2 CTAs per (b,k) map (352 CTAs x 256 threads, all co-resident).
// Cross-CTA argmax via packed u64 atomicMax: hi = ordered-uint(pooled),
// lo = ~idx (bigger lo  <=>  smaller idx  =>  first-occurrence ties).
// Last CTA (global counter) decodes all 176 winners, gathers pred, means.

#define BVAL 16
#define KVAL 11
#define NBK  (BVAL * KVAL)          // 176
#define NCTA (NBK * 2)              // 352
#define HVAL 128
#define WVAL 128
#define HW   (HVAL * WVAL)
#define CVAL 7
#define NTHREADS 256                // 8 warps; warp owns 8 rows of its 64-row half
#define NWARPS   (NTHREADS / 32)

__device__ unsigned long long g_labelloss_best[NBK];   // zero-init; reset by last CTA
__device__ unsigned int       g_labelloss_count = 0;

__device__ __forceinline__ unsigned int float_to_ordered(float f)
{
    unsigned int u = __float_as_uint(f);
    return (u & 0x80000000u) ? ~u : (u | 0x80000000u);  // monotone map, all > 0
}

__global__ __launch_bounds__(NTHREADS)
void labelloss_fused_kernel(const float* __restrict__ pred,
                            const float* __restrict__ gt,
                            const float* __restrict__ heatmap,
                            float* __restrict__ out)
{
    const int bid  = blockIdx.x;            // 0..351
    const int bk   = bid >> 1;              // b*K + k
    const int half = bid & 1;               // 0: rows 0-63, 1: rows 64-127
    const int tid  = threadIdx.x;
    const int lane = tid & 31;
    const int warp = tid >> 5;              // 0..7
    const int x0   = half * 64 + warp * 8;  // row strip start
    const int c0   = lane * 4;              // 4 columns per lane

    const float* __restrict__ hm = heatmap + (size_t)bk * HW;

    // ---- Phase 1: front-batch all loads (rows x0-1 .. x0+8) -> MLP = 10 ----
    float4 v[10];
    #pragma unroll
    for (int i = 0; i < 10; ++i) {
        const int x = x0 - 1 + i;
        if ((unsigned)x < (unsigned)HVAL) {
            v[i] = *reinterpret_cast<const float4*>(hm + x * WVAL + c0);
        } else {
            v[i] = make_float4(0.f, 0.f, 0.f, 0.f);
        }
    }

    // ---- Phase 2: horizontal 3-tap per row ----
    float4 rs[10];
    #pragma unroll
    for (int i = 0; i < 10; ++i) {
        float left  = __shfl_up_sync(0xffffffffu, v[i].w, 1);
        float right = __shfl_down_sync(0xffffffffu, v[i].x, 1);
        if (lane == 0)  left  = 0.f;
        if (lane == 31) right = 0.f;
        rs[i].x = left    + v[i].x + v[i].y;
        rs[i].y = v[i].x  + v[i].y + v[i].z;
        rs[i].z = v[i].y  + v[i].z + v[i].w;
        rs[i].w = v[i].z  + v[i].w + right;
    }

    // ---- Phase 3: vertical 3-tap + per-thread argmax ----
    float best = -FLT_MAX;
    int   bidx = 0x7FFFFFFF;
    #pragma unroll
    for (int j = 0; j < 8; ++j) {
        const int x = x0 + j;
        float p0 = rs[j].x + rs[j + 1].x + rs[j + 2].x;
        float p1 = rs[j].y + rs[j + 1].y + rs[j + 2].y;
        float p2 = rs[j].z + rs[j + 1].z + rs[j + 2].z;
        float p3 = rs[j].w + rs[j + 1].w + rs[j + 2].w;
        const int base = x * WVAL + c0;
        if (p0 > best) { best = p0; bidx = base;     }
        if (p1 > best) { best = p1; bidx = base + 1; }
        if (p2 > best) { best = p2; bidx = base + 2; }
        if (p3 > best) { best = p3; bidx = base + 3; }
    }

    // ---- Phase 4: warp reduce, then CTA reduce via smem (ties -> smaller idx) ----
    #pragma unroll
    for (int off = 16; off > 0; off >>= 1) {
        float v2 = __shfl_down_sync(0xffffffffu, best, off);
        int   i2 = __shfl_down_sync(0xffffffffu, bidx, off);
        if (v2 > best || (v2 == best && i2 < bidx)) { best = v2; bidx = i2; }
    }

    __shared__ float swv[NWARPS];
    __shared__ int   swi[NWARPS];
    __shared__ bool  is_last;
    if (lane == 0) { swv[warp] = best; swi[warp] = bidx; }
    __syncthreads();

    if (tid == 0) {
        best = swv[0]; bidx = swi[0];
        #pragma unroll
        for (int w = 1; w < NWARPS; ++w) {
            float v2 = swv[w]; int i2 = swi[w];
            if (v2 > best || (v2 == best && i2 < bidx)) { best = v2; bidx = i2; }
        }
        unsigned long long packed =
            ((unsigned long long)float_to_ordered(best) << 32) |
            (unsigned long long)(~(unsigned int)bidx);
        atomicMax(&g_labelloss_best[bk], packed);
        __threadfence();                                  // best visible before count
        unsigned cnt = atomicAdd(&g_labelloss_count, 1u);
        is_last = (cnt == NCTA - 1);
    }
    __syncthreads();

    // ---- Phase 5: last CTA computes all 176 losses in parallel, then means ----
    if (is_last) {
        __threadfence();                                  // acquire all atomicMax results
        __shared__ float sloss[NBK];
        if (tid < NBK) {
            unsigned long long packed = g_labelloss_best[tid];
            const int idx = (int)(~(unsigned int)(packed & 0xFFFFFFFFull));
            const float* __restrict__ pk = pred + (size_t)tid * CVAL * HW;
            const float* __restrict__ g  = gt   + (size_t)tid * CVAL;
            float loss = 0.0f;
            #pragma unroll
            for (int c = 0; c < CVAL; ++c) {
                float d = pk[c * HW + idx] - g[c];
                loss = fmaf(d, d, loss);
            }
            sloss[tid] = loss;
            g_labelloss_best[tid] = 0ull;                 // reset for next replay
        }
        __syncthreads();
        if (tid < BVAL) {
            float s = 0.0f;
            #pragma unroll
            for (int k = 0; k < KVAL; ++k)
                s += sloss[tid * KVAL + k];               // fixed order: deterministic
            out[tid] = s * (1.0f / (float)KVAL);
        }
        if (tid == 0) g_labelloss_count = 0;              // reset for next replay
    }
}

extern "C" void kernel_launch(void* const* d_in, const int* in_sizes, int n_in,
                              void* d_out, int out_size)
{
    const float* pred    = (const float*)d_in[0];
    const float* gt      = (const float*)d_in[1];
    const float* heatmap = (const float*)d_in[2];
    float* out = (float*)d_out;

    labelloss_fused_kernel<<<NCTA, NTHREADS>>>(pred, gt, heatmap, out);
}